// round 1
// baseline (speedup 1.0000x reference)
#include <cuda_runtime.h>
#include <cuda_bf16.h>
#include <math.h>

// ---------------------------------------------------------------------------
// Set2Set readout: 6 iterations of {attention softmax readout, LSTM cell}.
//   x: (N,256) fp32, batch: (N,) int32 sorted, G graphs.
//   out: (G, 512) = concat(h_final, readout_final)
// ---------------------------------------------------------------------------

#define DIM 256
#define GDIM4 1024          // 4*DIM
#define KCAT 512            // 2*DIM
#define MAXG 8192
#define MAXN 200000

// persistent scratch (device globals; no allocation allowed)
__device__ int   g_offs[MAXG + 1];
__device__ float g_Acat[MAXG * KCAT];        // [readout(256) | h(256)] per graph
__device__ float g_Wcat[GDIM4 * KCAT];       // [W_ih | W_hh] rows of 512
__device__ float g_bsum[GDIM4];
__device__ float g_gates[(size_t)MAXG * GDIM4];
__device__ float g_c[MAXG * DIM];

// --------------------------- prep kernels ---------------------------------
__global__ void prep_w_kernel(const float* __restrict__ W_ih,
                              const float* __restrict__ W_hh,
                              const float* __restrict__ b_ih,
                              const float* __restrict__ b_hh) {
    int idx = blockIdx.x * blockDim.x + threadIdx.x;
    if (idx < GDIM4 * KCAT) {
        int n = idx / KCAT, k = idx % KCAT;
        g_Wcat[idx] = (k < DIM) ? W_ih[n * DIM + k] : W_hh[n * DIM + (k - DIM)];
    }
    if (idx < GDIM4) g_bsum[idx] = b_ih[idx] + b_hh[idx];
}

// CSR offsets from sorted batch. offs[g] = first index with batch >= g.
__global__ void offsets_kernel(const int* __restrict__ batch, int N, int G) {
    int i = blockIdx.x * blockDim.x + threadIdx.x;
    if (i >= N) return;
    int cur = batch[i];
    if (i == 0) {
        for (int g = 0; g <= cur; ++g) g_offs[g] = 0;
    } else {
        int prev = batch[i - 1];
        for (int g = prev + 1; g <= cur; ++g) g_offs[g] = i;
    }
    if (i == N - 1) {
        for (int g = cur + 1; g <= G; ++g) g_offs[g] = N;
    }
}

__global__ void zero_state_kernel(int G) {
    int idx = blockIdx.x * blockDim.x + threadIdx.x;
    if (idx >= G * DIM) return;
    int g = idx >> 8, d = idx & 255;
    g_c[idx] = 0.f;
    g_Acat[g * KCAT + DIM + d] = 0.f;   // h = 0
}

// --------------------- fused attention + readout --------------------------
// One warp per graph; lane l owns dims {l, l+32, ..., l+224}.
// Online softmax with max initialized to 0 (matches torch scatter amax w/ 0 init).
__global__ void attn_kernel(const float* __restrict__ x, int G) {
    int warp = (blockIdx.x * blockDim.x + threadIdx.x) >> 5;
    int lane = threadIdx.x & 31;
    if (warp >= G) return;

    int vs = g_offs[warp], ve = g_offs[warp + 1];

    float h[8], acc[8];
    const float* hrow = g_Acat + warp * KCAT + DIM;
#pragma unroll
    for (int j = 0; j < 8; ++j) { h[j] = hrow[lane + 32 * j]; acc[j] = 0.f; }

    float m = 0.f, d = 0.f;
    for (int v = vs; v < ve; ++v) {
        const float* xr = x + (size_t)v * DIM;
        float xv[8];
        float p = 0.f;
#pragma unroll
        for (int j = 0; j < 8; ++j) {
            xv[j] = xr[lane + 32 * j];
            p = fmaf(xv[j], h[j], p);
        }
#pragma unroll
        for (int o = 16; o; o >>= 1) p += __shfl_xor_sync(0xffffffffu, p, o);

        float mn = fmaxf(m, p);
        float sc = expf(m - mn);     // 1.0 when max unchanged
        float pe = expf(p - mn);
        d = d * sc + pe;
#pragma unroll
        for (int j = 0; j < 8; ++j) acc[j] = fmaf(acc[j], sc, xv[j] * pe);
        m = mn;
    }

    float inv = 1.f / (d + 1e-8f);
    float* ro = g_Acat + warp * KCAT;     // readout slot (also GEMM A input)
#pragma unroll
    for (int j = 0; j < 8; ++j) ro[lane + 32 * j] = acc[j] * inv;
}

// ------------------------------ SGEMM --------------------------------------
// C[M][N] = A[M][K] * B[N][K]^T + bias[n]   (M=G, N=1024, K=512)
// 128x128 block tile, BK=16, 256 threads, 8x8 microtile per thread.
__global__ void __launch_bounds__(256)
sgemm_kernel(const float* __restrict__ A, const float* __restrict__ B,
             const float* __restrict__ bias, float* __restrict__ C,
             int M, int N, int K) {
    const int BM = 128, BN = 128, BK = 16, TM = 8, TN = 8;
    __shared__ float As[BK][BM];
    __shared__ float Bs[BK][BN];

    int tid = threadIdx.x;
    int tCol = tid % 16;       // 16 cols * TN(8) = 128
    int tRow = tid / 16;       // 16 rows * TM(8) = 128

    const float* Ab = A + (size_t)blockIdx.y * BM * K;
    const float* Bb = B + (size_t)blockIdx.x * BN * K;

    int lRow = tid / 4;            // 0..63
    int lCol = (tid % 4) * 4;      // 0,4,8,12

    float acc[TM][TN];
#pragma unroll
    for (int i = 0; i < TM; ++i)
#pragma unroll
        for (int j = 0; j < TN; ++j) acc[i][j] = 0.f;

    for (int k0 = 0; k0 < K; k0 += BK) {
#pragma unroll
        for (int r = 0; r < 2; ++r) {
            int row = lRow + 64 * r;
            float4 va = *(const float4*)(Ab + (size_t)row * K + k0 + lCol);
            As[lCol + 0][row] = va.x;
            As[lCol + 1][row] = va.y;
            As[lCol + 2][row] = va.z;
            As[lCol + 3][row] = va.w;
            float4 vb = *(const float4*)(Bb + (size_t)row * K + k0 + lCol);
            Bs[lCol + 0][row] = vb.x;
            Bs[lCol + 1][row] = vb.y;
            Bs[lCol + 2][row] = vb.z;
            Bs[lCol + 3][row] = vb.w;
        }
        __syncthreads();

#pragma unroll
        for (int kk = 0; kk < BK; ++kk) {
            float ra[TM], rb[TN];
#pragma unroll
            for (int i = 0; i < TM; ++i) ra[i] = As[kk][tRow * TM + i];
#pragma unroll
            for (int j = 0; j < TN; ++j) rb[j] = Bs[kk][tCol * TN + j];
#pragma unroll
            for (int i = 0; i < TM; ++i)
#pragma unroll
                for (int j = 0; j < TN; ++j)
                    acc[i][j] = fmaf(ra[i], rb[j], acc[i][j]);
        }
        __syncthreads();
    }

    int cRow = blockIdx.y * BM + tRow * TM;
    int cCol = blockIdx.x * BN + tCol * TN;
#pragma unroll
    for (int i = 0; i < TM; ++i) {
        float* crow = C + (size_t)(cRow + i) * N + cCol;
#pragma unroll
        for (int j = 0; j < TN; ++j)
            crow[j] = acc[i][j] + bias[cCol + j];
    }
}

// ------------------------- pointwise LSTM ---------------------------------
__device__ __forceinline__ float sigm(float v) { return 1.f / (1.f + expf(-v)); }

__global__ void lstm_kernel(float* __restrict__ out, int G, int last) {
    int idx = blockIdx.x * blockDim.x + threadIdx.x;
    if (idx >= G * DIM) return;
    int g = idx >> 8, d = idx & 255;
    const float* gr = g_gates + (size_t)g * GDIM4;
    float gi = sigm(gr[d]);
    float gf = sigm(gr[DIM + d]);
    float gg = tanhf(gr[2 * DIM + d]);
    float go = sigm(gr[3 * DIM + d]);
    float c = gf * g_c[idx] + gi * gg;
    float h = go * tanhf(c);
    g_c[idx] = c;
    g_Acat[g * KCAT + DIM + d] = h;
    if (last) {
        out[(size_t)g * 512 + d]       = h;                      // h half
        out[(size_t)g * 512 + 256 + d] = g_Acat[g * KCAT + d];   // readout half
    }
}

// ------------------------------ launch -------------------------------------
extern "C" void kernel_launch(void* const* d_in, const int* in_sizes, int n_in,
                              void* d_out, int out_size) {
    const float* x     = (const float*)d_in[0];
    const int*   batch = (const int*)d_in[1];
    // d_in[2] = n_graphs scalar (device); derive G from out_size instead
    const float* W_ih  = (const float*)d_in[3];
    const float* W_hh  = (const float*)d_in[4];
    const float* b_ih  = (const float*)d_in[5];
    const float* b_hh  = (const float*)d_in[6];
    float* out = (float*)d_out;

    int N = in_sizes[1];
    int G = out_size / (2 * DIM);

    prep_w_kernel<<<(GDIM4 * KCAT + 255) / 256, 256>>>(W_ih, W_hh, b_ih, b_hh);
    offsets_kernel<<<(N + 255) / 256, 256>>>(batch, N, G);
    zero_state_kernel<<<(G * DIM + 255) / 256, 256>>>(G);

    float* Acat;  cudaGetSymbolAddress((void**)&Acat, g_Acat);
    float* Wcat;  cudaGetSymbolAddress((void**)&Wcat, g_Wcat);
    float* bsum;  cudaGetSymbolAddress((void**)&bsum, g_bsum);
    float* gates; cudaGetSymbolAddress((void**)&gates, g_gates);

    dim3 gemm_grid(GDIM4 / 128, (G + 127) / 128);
    for (int it = 0; it < 6; ++it) {
        attn_kernel<<<(G * 32 + 255) / 256, 256>>>(x, G);
        sgemm_kernel<<<gemm_grid, 256>>>(Acat, Wcat, bsum, gates, G, GDIM4, KCAT);
        lstm_kernel<<<(G * DIM + 255) / 256, 256>>>(out, G, it == 5 ? 1 : 0);
    }
}

// round 3
// speedup vs baseline: 2.4604x; 2.4604x over previous
#include <cuda_runtime.h>
#include <cuda_bf16.h>
#include <math.h>
#include <cstdint>

// ---------------------------------------------------------------------------
// Set2Set readout, 6 iterations of {attention readout, LSTM}.
// GEMM via mma.sync tf32 (plain-PTX-target safe), LSTM fused into epilogue.
// Gate-interleaved weights (row = 4*d + q); A ping-pongs between two buffers.
// ---------------------------------------------------------------------------

#define DIM 256
#define GDIM4 1024          // 4*DIM gate cols
#define KCAT 512            // GEMM K
#define MAXG 8192

__device__ int   g_offs[MAXG + 1];
__device__ float g_A0[MAXG * KCAT];     // [readout(256) | h(256)], tf32-rounded
__device__ float g_A1[MAXG * KCAT];
__device__ float g_Wcat[GDIM4 * KCAT];  // gate-interleaved, tf32-rounded
__device__ float g_bsum[GDIM4];
__device__ float g_c[MAXG * DIM];

// ----------------------------- helpers ------------------------------------
__device__ __forceinline__ uint32_t smem_u32(const void* p) {
    uint32_t a;
    asm("{ .reg .u64 t; cvta.to.shared.u64 t, %1; cvt.u32.u64 %0, t; }"
        : "=r"(a) : "l"(p));
    return a;
}
__device__ __forceinline__ float tf32r(float x) {
    uint32_t u;
    asm("cvt.rna.tf32.f32 %0, %1;" : "=r"(u) : "f"(x));
    return __uint_as_float(u);
}
__device__ __forceinline__ float sigm(float v) { return 1.f / (1.f + __expf(-v)); }

#define LDS32(r, a) asm volatile("ld.shared.b32 %0, [%1];" : "=r"(r) : "r"(a))
#define CP_ASYNC16(dst, src) \
    asm volatile("cp.async.cg.shared.global [%0], [%1], 16;" :: "r"(dst), "l"(src) : "memory")
#define CP_COMMIT() asm volatile("cp.async.commit_group;" ::: "memory")

__device__ __forceinline__ void mma_tf32(float* c, const uint32_t* a, const uint32_t* b) {
    asm volatile(
        "mma.sync.aligned.m16n8k8.row.col.f32.tf32.tf32.f32 "
        "{%0,%1,%2,%3}, {%4,%5,%6,%7}, {%8,%9}, {%0,%1,%2,%3};"
        : "+f"(c[0]), "+f"(c[1]), "+f"(c[2]), "+f"(c[3])
        : "r"(a[0]), "r"(a[1]), "r"(a[2]), "r"(a[3]), "r"(b[0]), "r"(b[1]));
}

// --------------------------- prep kernels ---------------------------------
// New W row r = 4*d + q from original gate row n = q*256 + d; tf32-rounded.
__global__ void prep_w_kernel(const float* __restrict__ W_ih,
                              const float* __restrict__ W_hh,
                              const float* __restrict__ b_ih,
                              const float* __restrict__ b_hh) {
    int idx = blockIdx.x * blockDim.x + threadIdx.x;
    if (idx < GDIM4 * KCAT) {
        int r = idx / KCAT, k = idx % KCAT;
        int d = r >> 2, q = r & 3;
        int n = q * DIM + d;
        float w = (k < DIM) ? W_ih[n * DIM + k] : W_hh[n * DIM + (k - DIM)];
        g_Wcat[idx] = tf32r(w);
        if (k == 0) g_bsum[r] = b_ih[n] + b_hh[n];
    }
}

__global__ void offsets_kernel(const int* __restrict__ batch, int N, int G) {
    int i = blockIdx.x * blockDim.x + threadIdx.x;
    if (i >= N) return;
    int cur = batch[i];
    if (i == 0) { for (int g = 0; g <= cur; ++g) g_offs[g] = 0; }
    else { int prev = batch[i - 1]; for (int g = prev + 1; g <= cur; ++g) g_offs[g] = i; }
    if (i == N - 1) { for (int g = cur + 1; g <= G; ++g) g_offs[g] = N; }
}

__global__ void zero_state_kernel(int G) {
    int idx = blockIdx.x * blockDim.x + threadIdx.x;
    if (idx >= G * DIM) return;
    int g = idx >> 8, d = idx & 255;
    g_c[idx] = 0.f;
    g_A0[g * KCAT + DIM + d] = 0.f;
}

// --------------------- fused attention + readout --------------------------
// One warp per graph; float4 lanes, 2-node unroll, online softmax (m0 = 0).
__global__ void attn_kernel(const float* __restrict__ x, float* __restrict__ buf,
                            float* __restrict__ out, int G, int last) {
    int warp = (blockIdx.x * blockDim.x + threadIdx.x) >> 5;
    int lane = threadIdx.x & 31;
    if (warp >= G) return;
    int vs = g_offs[warp], ve = g_offs[warp + 1];

    const float4* hb = (const float4*)(buf + (size_t)warp * KCAT + DIM);
    float4 h0 = hb[lane], h1 = hb[lane + 32];
    float4 a0 = {0.f, 0.f, 0.f, 0.f}, a1 = {0.f, 0.f, 0.f, 0.f};
    float m = 0.f, dd = 0.f;

    int v = vs;
    for (; v + 1 < ve; v += 2) {
        const float4* xA = (const float4*)(x + (size_t)v * DIM);
        const float4* xB = (const float4*)(x + (size_t)(v + 1) * DIM);
        float4 A0 = xA[lane], A1 = xA[lane + 32];
        float4 B0 = xB[lane], B1 = xB[lane + 32];
        float pA = A0.x * h0.x; pA = fmaf(A0.y, h0.y, pA); pA = fmaf(A0.z, h0.z, pA);
        pA = fmaf(A0.w, h0.w, pA); pA = fmaf(A1.x, h1.x, pA); pA = fmaf(A1.y, h1.y, pA);
        pA = fmaf(A1.z, h1.z, pA); pA = fmaf(A1.w, h1.w, pA);
        float pB = B0.x * h0.x; pB = fmaf(B0.y, h0.y, pB); pB = fmaf(B0.z, h0.z, pB);
        pB = fmaf(B0.w, h0.w, pB); pB = fmaf(B1.x, h1.x, pB); pB = fmaf(B1.y, h1.y, pB);
        pB = fmaf(B1.z, h1.z, pB); pB = fmaf(B1.w, h1.w, pB);
#pragma unroll
        for (int o = 16; o; o >>= 1) {
            pA += __shfl_xor_sync(0xffffffffu, pA, o);
            pB += __shfl_xor_sync(0xffffffffu, pB, o);
        }
        float mn = fmaxf(m, fmaxf(pA, pB));
        float sc = __expf(m - mn), eA = __expf(pA - mn), eB = __expf(pB - mn);
        dd = dd * sc + eA + eB;
        a0.x = a0.x * sc + A0.x * eA + B0.x * eB;  a0.y = a0.y * sc + A0.y * eA + B0.y * eB;
        a0.z = a0.z * sc + A0.z * eA + B0.z * eB;  a0.w = a0.w * sc + A0.w * eA + B0.w * eB;
        a1.x = a1.x * sc + A1.x * eA + B1.x * eB;  a1.y = a1.y * sc + A1.y * eA + B1.y * eB;
        a1.z = a1.z * sc + A1.z * eA + B1.z * eB;  a1.w = a1.w * sc + A1.w * eA + B1.w * eB;
        m = mn;
    }
    if (v < ve) {
        const float4* xA = (const float4*)(x + (size_t)v * DIM);
        float4 A0 = xA[lane], A1 = xA[lane + 32];
        float pA = A0.x * h0.x; pA = fmaf(A0.y, h0.y, pA); pA = fmaf(A0.z, h0.z, pA);
        pA = fmaf(A0.w, h0.w, pA); pA = fmaf(A1.x, h1.x, pA); pA = fmaf(A1.y, h1.y, pA);
        pA = fmaf(A1.z, h1.z, pA); pA = fmaf(A1.w, h1.w, pA);
#pragma unroll
        for (int o = 16; o; o >>= 1) pA += __shfl_xor_sync(0xffffffffu, pA, o);
        float mn = fmaxf(m, pA);
        float sc = __expf(m - mn), eA = __expf(pA - mn);
        dd = dd * sc + eA;
        a0.x = a0.x * sc + A0.x * eA;  a0.y = a0.y * sc + A0.y * eA;
        a0.z = a0.z * sc + A0.z * eA;  a0.w = a0.w * sc + A0.w * eA;
        a1.x = a1.x * sc + A1.x * eA;  a1.y = a1.y * sc + A1.y * eA;
        a1.z = a1.z * sc + A1.z * eA;  a1.w = a1.w * sc + A1.w * eA;
        m = mn;
    }
    float inv = 1.f / (dd + 1e-8f);
    a0.x *= inv; a0.y *= inv; a0.z *= inv; a0.w *= inv;
    a1.x *= inv; a1.y *= inv; a1.z *= inv; a1.w *= inv;
    if (last) {   // exact fp32 readout to output
        float4* o4 = (float4*)(out + (size_t)warp * 512 + DIM);
        o4[lane] = a0; o4[lane + 32] = a1;
    }
    // tf32-rounded copy for the GEMM
    float4 r0, r1;
    r0.x = tf32r(a0.x); r0.y = tf32r(a0.y); r0.z = tf32r(a0.z); r0.w = tf32r(a0.w);
    r1.x = tf32r(a1.x); r1.y = tf32r(a1.y); r1.z = tf32r(a1.z); r1.w = tf32r(a1.w);
    float4* ro = (float4*)(buf + (size_t)warp * KCAT);
    ro[lane] = r0; ro[lane + 32] = r1;
}

// ------------------- mma.sync tf32 GEMM + fused LSTM -----------------------
// C[M][1024] = A[M][512] * Wcat[1024][512]^T ; CTA tile 128x128, 8 warps,
// warp tile 32x64, BK=32, 3-stage cp.async pipeline.
#define NSTAGE 3
#define SA 36                          // padded row stride (floats): banks 4r+c
#define A_BYTES (128 * SA * 4)         // 18432
#define STAGE_BYTES (2 * A_BYTES)      // 36864
#define GEMM_SMEM (NSTAGE * STAGE_BYTES)

__global__ void __launch_bounds__(256, 2)
gemm_lstm_kernel(const float* __restrict__ A, float* __restrict__ Anext,
                 float* __restrict__ out, int M, int last) {
    extern __shared__ __align__(128) char smem[];
    uint32_t sbase = smem_u32(smem);
    const int tid = threadIdx.x;
    const int wid = tid >> 5, lane = tid & 31;
    const int wm = wid & 3, wn = wid >> 2;      // 4x2 warp grid
    const int bn = blockIdx.x, bm = blockIdx.y;

    // loader: chunk c (k offset c*32) into stage s
    auto load_chunk = [&](int c, int s) {
#pragma unroll
        for (int i = 0; i < 8; ++i) {
            int q = i * 256 + tid;
            int tile = q >> 10;          // 0 = A, 1 = B
            int idx = q & 1023;
            int row = idx >> 3, c4 = idx & 7;
            uint32_t dst = sbase + s * STAGE_BYTES + tile * A_BYTES
                         + (uint32_t)(row * SA + c4 * 4) * 4;
            const float* src;
            if (tile == 0) {
                int rA = bm * 128 + row; if (rA >= M) rA = M - 1;
                src = A + (size_t)rA * KCAT + c * 32 + c4 * 4;
            } else {
                src = g_Wcat + (size_t)(bn * 128 + row) * KCAT + c * 32 + c4 * 4;
            }
            CP_ASYNC16(dst, src);
        }
        CP_COMMIT();
    };

#pragma unroll
    for (int s = 0; s < NSTAGE; ++s) load_chunk(s, s);

    float acc[2][8][4];
#pragma unroll
    for (int mt = 0; mt < 2; ++mt)
#pragma unroll
        for (int nt = 0; nt < 8; ++nt)
#pragma unroll
            for (int r = 0; r < 4; ++r) acc[mt][nt][r] = 0.f;

    // fragment base addresses (stage-relative)
    const uint32_t a_rel = (uint32_t)((wm * 32 + (lane >> 2)) * SA + (lane & 3)) * 4;
    const uint32_t b_rel = (uint32_t)((wn * 64 + (lane >> 2)) * SA + (lane & 3)) * 4;

    for (int c = 0; c < 16; ++c) {
        const int s = c % NSTAGE;
        asm volatile("cp.async.wait_group %0;" :: "n"(NSTAGE - 1) : "memory");
        __syncthreads();
        uint32_t aS = sbase + s * STAGE_BYTES + a_rel;
        uint32_t bS = sbase + s * STAGE_BYTES + A_BYTES + b_rel;
#pragma unroll
        for (int kk = 0; kk < 4; ++kk) {
            uint32_t af[2][4], bf[8][2];
#pragma unroll
            for (int mt = 0; mt < 2; ++mt) {
                uint32_t base = aS + (uint32_t)(mt * 16 * SA + kk * 8) * 4;
                LDS32(af[mt][0], base);
                LDS32(af[mt][1], base + 8 * SA * 4);
                LDS32(af[mt][2], base + 16);
                LDS32(af[mt][3], base + 8 * SA * 4 + 16);
            }
#pragma unroll
            for (int nt = 0; nt < 8; ++nt) {
                uint32_t base = bS + (uint32_t)(nt * 8 * SA + kk * 8) * 4;
                LDS32(bf[nt][0], base);
                LDS32(bf[nt][1], base + 16);
            }
#pragma unroll
            for (int mt = 0; mt < 2; ++mt)
#pragma unroll
                for (int nt = 0; nt < 8; ++nt)
                    mma_tf32(acc[mt][nt], af[mt], bf[nt]);
        }
        if (c + NSTAGE < 16) {
            __syncthreads();
            load_chunk(c + NSTAGE, s);
        }
    }

    // ---- epilogue: bias + LSTM; gate-interleaved cols (col = 4*d + q) ----
    const int sub = lane & 3;
    const bool odd = sub & 1;
    const int dhalf = sub >> 1;
#pragma unroll
    for (int mt = 0; mt < 2; ++mt) {
        int g = bm * 128 + wm * 32 + mt * 16 + (lane >> 2) + (odd ? 8 : 0);
#pragma unroll
        for (int nt = 0; nt < 8; ++nt) {
            float c0 = acc[mt][nt][0], c1 = acc[mt][nt][1];
            float c2 = acc[mt][nt][2], c3 = acc[mt][nt][3];
            int colb = bn * 128 + wn * 64 + nt * 8 + sub * 2;
            float bi0 = __ldg(g_bsum + colb), bi1 = __ldg(g_bsum + colb + 1);
            c0 += bi0; c1 += bi1; c2 += bi0; c3 += bi1;
            float t0 = __shfl_xor_sync(0xffffffffu, c0, 1);
            float t1 = __shfl_xor_sync(0xffffffffu, c1, 1);
            float t2 = __shfl_xor_sync(0xffffffffu, c2, 1);
            float t3 = __shfl_xor_sync(0xffffffffu, c3, 1);
            float gi = odd ? t2 : c0;
            float gf = odd ? t3 : c1;
            float gg = odd ? c2 : t0;
            float go = odd ? c3 : t1;
            int d = ((bn * 128 + wn * 64 + nt * 8) >> 2) + dhalf;
            if (g < M) {
                float cold = g_c[g * DIM + d];
                float cn = sigm(gf) * cold + sigm(gi) * tanhf(gg);
                float h = sigm(go) * tanhf(cn);
                g_c[g * DIM + d] = cn;
                Anext[(size_t)g * KCAT + DIM + d] = tf32r(h);
                if (last) out[(size_t)g * 512 + d] = h;
            }
        }
    }
}

// ------------------------------ launch -------------------------------------
extern "C" void kernel_launch(void* const* d_in, const int* in_sizes, int n_in,
                              void* d_out, int out_size) {
    const float* x     = (const float*)d_in[0];
    const int*   batch = (const int*)d_in[1];
    const float* W_ih  = (const float*)d_in[3];
    const float* W_hh  = (const float*)d_in[4];
    const float* b_ih  = (const float*)d_in[5];
    const float* b_hh  = (const float*)d_in[6];
    float* out = (float*)d_out;

    int N = in_sizes[1];
    int G = out_size / (2 * DIM);

    float *A0, *A1;
    cudaGetSymbolAddress((void**)&A0, g_A0);
    cudaGetSymbolAddress((void**)&A1, g_A1);

    cudaFuncSetAttribute(gemm_lstm_kernel,
                         cudaFuncAttributeMaxDynamicSharedMemorySize, GEMM_SMEM);

    prep_w_kernel<<<(GDIM4 * KCAT + 255) / 256, 256>>>(W_ih, W_hh, b_ih, b_hh);
    offsets_kernel<<<(N + 255) / 256, 256>>>(batch, N, G);
    zero_state_kernel<<<(G * DIM + 255) / 256, 256>>>(G);

    dim3 gemm_grid(GDIM4 / 128, (G + 127) / 128);
    for (int it = 0; it < 6; ++it) {
        float* cur = (it & 1) ? A1 : A0;
        float* nxt = (it & 1) ? A0 : A1;
        int last = (it == 5) ? 1 : 0;
        attn_kernel<<<(G * 32 + 255) / 256, 256>>>(x, cur, out, G, last);
        gemm_lstm_kernel<<<gemm_grid, 256, GEMM_SMEM>>>(cur, nxt, out, G, last);
    }
}

// round 4
// speedup vs baseline: 2.6993x; 1.0971x over previous
#include <cuda_runtime.h>
#include <cuda_bf16.h>
#include <math.h>
#include <cstdint>

// ---------------------------------------------------------------------------
// Set2Set readout, 6 iterations of {attention readout, LSTM}.
// GEMM via mma.sync tf32, swizzled smem (2 CTAs/SM), LSTM fused into epilogue.
// ---------------------------------------------------------------------------

#define DIM 256
#define GDIM4 1024
#define KCAT 512
#define MAXG 8192

__device__ int   g_offs[MAXG + 1];
__device__ float g_A0[MAXG * KCAT];     // [readout(256) | h(256)], tf32-rounded
__device__ float g_A1[MAXG * KCAT];
__device__ float g_Wcat[GDIM4 * KCAT];  // gate-interleaved rows: r = 4*d + q
__device__ float g_bsum[GDIM4];
__device__ float g_c[MAXG * DIM];

// ----------------------------- helpers ------------------------------------
__device__ __forceinline__ uint32_t smem_u32(const void* p) {
    uint32_t a;
    asm("{ .reg .u64 t; cvta.to.shared.u64 t, %1; cvt.u32.u64 %0, t; }"
        : "=r"(a) : "l"(p));
    return a;
}
__device__ __forceinline__ float tf32r(float x) {
    uint32_t u;
    asm("cvt.rna.tf32.f32 %0, %1;" : "=r"(u) : "f"(x));
    return __uint_as_float(u);
}
__device__ __forceinline__ float sigm(float v) { return 1.f / (1.f + __expf(-v)); }
__device__ __forceinline__ float ftanh(float v) {
    float e = __expf(2.f * v);
    return 1.f - 2.f / (e + 1.f);
}

#define LDS32(r, a) asm volatile("ld.shared.b32 %0, [%1];" : "=r"(r) : "r"(a))
#define CP_ASYNC16(dst, src) \
    asm volatile("cp.async.cg.shared.global [%0], [%1], 16;" :: "r"(dst), "l"(src) : "memory")
#define CP_COMMIT() asm volatile("cp.async.commit_group;" ::: "memory")

__device__ __forceinline__ void mma_tf32(float* c, const uint32_t* a, const uint32_t* b) {
    asm volatile(
        "mma.sync.aligned.m16n8k8.row.col.f32.tf32.tf32.f32 "
        "{%0,%1,%2,%3}, {%4,%5,%6,%7}, {%8,%9}, {%0,%1,%2,%3};"
        : "+f"(c[0]), "+f"(c[1]), "+f"(c[2]), "+f"(c[3])
        : "r"(a[0]), "r"(a[1]), "r"(a[2]), "r"(a[3]), "r"(b[0]), "r"(b[1]));
}

// --------------------------- prep kernels ---------------------------------
__global__ void prep_w_kernel(const float* __restrict__ W_ih,
                              const float* __restrict__ W_hh,
                              const float* __restrict__ b_ih,
                              const float* __restrict__ b_hh) {
    int idx = blockIdx.x * blockDim.x + threadIdx.x;
    if (idx < GDIM4 * KCAT) {
        int r = idx / KCAT, k = idx % KCAT;
        int d = r >> 2, q = r & 3;
        int n = q * DIM + d;
        float w = (k < DIM) ? W_ih[n * DIM + k] : W_hh[n * DIM + (k - DIM)];
        g_Wcat[idx] = tf32r(w);
        if (k == 0) g_bsum[r] = b_ih[n] + b_hh[n];
    }
}

__global__ void offsets_kernel(const int* __restrict__ batch, int N, int G) {
    int i = blockIdx.x * blockDim.x + threadIdx.x;
    if (i >= N) return;
    int cur = batch[i];
    if (i == 0) { for (int g = 0; g <= cur; ++g) g_offs[g] = 0; }
    else { int prev = batch[i - 1]; for (int g = prev + 1; g <= cur; ++g) g_offs[g] = i; }
    if (i == N - 1) { for (int g = cur + 1; g <= G; ++g) g_offs[g] = N; }
}

__global__ void zero_state_kernel(int G) {
    int idx = blockIdx.x * blockDim.x + threadIdx.x;
    if (idx >= G * DIM) return;
    int g = idx >> 8, d = idx & 255;
    g_c[idx] = 0.f;
    g_A0[g * KCAT + DIM + d] = 0.f;
}

// --------------------- fused attention + readout --------------------------
// One warp per graph; 4-node unroll for MLP=16; online softmax (m0 = 0).
__device__ __forceinline__ float dot8(float4 a0, float4 a1, float4 h0, float4 h1) {
    float p = a0.x * h0.x;
    p = fmaf(a0.y, h0.y, p); p = fmaf(a0.z, h0.z, p); p = fmaf(a0.w, h0.w, p);
    p = fmaf(a1.x, h1.x, p); p = fmaf(a1.y, h1.y, p);
    p = fmaf(a1.z, h1.z, p); p = fmaf(a1.w, h1.w, p);
    return p;
}
__device__ __forceinline__ void scale4(float4& a, float s) {
    a.x *= s; a.y *= s; a.z *= s; a.w *= s;
}
__device__ __forceinline__ void fma4(float4& a, float4 x, float e) {
    a.x = fmaf(x.x, e, a.x); a.y = fmaf(x.y, e, a.y);
    a.z = fmaf(x.z, e, a.z); a.w = fmaf(x.w, e, a.w);
}

__global__ void __launch_bounds__(128)
attn_kernel(const float* __restrict__ x, float* __restrict__ buf,
            float* __restrict__ out, int G, int last) {
    int warp = (blockIdx.x * blockDim.x + threadIdx.x) >> 5;
    int lane = threadIdx.x & 31;
    if (warp >= G) return;
    int vs = g_offs[warp], ve = g_offs[warp + 1];

    const float4* hb = (const float4*)(buf + (size_t)warp * KCAT + DIM);
    float4 h0 = hb[lane], h1 = hb[lane + 32];
    float4 a0 = {0.f, 0.f, 0.f, 0.f}, a1 = {0.f, 0.f, 0.f, 0.f};
    float m = 0.f, dd = 0.f;

    int v = vs;
    for (; v + 3 < ve; v += 4) {
        float4 X0[4], X1[4];
        float p[4];
#pragma unroll
        for (int i = 0; i < 4; ++i) {
            const float4* xr = (const float4*)(x + (size_t)(v + i) * DIM);
            X0[i] = xr[lane]; X1[i] = xr[lane + 32];
        }
#pragma unroll
        for (int i = 0; i < 4; ++i) p[i] = dot8(X0[i], X1[i], h0, h1);
#pragma unroll
        for (int o = 16; o; o >>= 1) {
#pragma unroll
            for (int i = 0; i < 4; ++i)
                p[i] += __shfl_xor_sync(0xffffffffu, p[i], o);
        }
        float mn = fmaxf(fmaxf(fmaxf(p[0], p[1]), fmaxf(p[2], p[3])), m);
        float sc = __expf(m - mn);
        float e[4];
#pragma unroll
        for (int i = 0; i < 4; ++i) e[i] = __expf(p[i] - mn);
        dd = dd * sc + e[0] + e[1] + e[2] + e[3];
        scale4(a0, sc); scale4(a1, sc);
#pragma unroll
        for (int i = 0; i < 4; ++i) { fma4(a0, X0[i], e[i]); fma4(a1, X1[i], e[i]); }
        m = mn;
    }
    for (; v < ve; ++v) {
        const float4* xr = (const float4*)(x + (size_t)v * DIM);
        float4 X0 = xr[lane], X1 = xr[lane + 32];
        float p = dot8(X0, X1, h0, h1);
#pragma unroll
        for (int o = 16; o; o >>= 1) p += __shfl_xor_sync(0xffffffffu, p, o);
        float mn = fmaxf(m, p);
        float sc = __expf(m - mn), e = __expf(p - mn);
        dd = dd * sc + e;
        scale4(a0, sc); scale4(a1, sc);
        fma4(a0, X0, e); fma4(a1, X1, e);
        m = mn;
    }
    float inv = 1.f / (dd + 1e-8f);
    scale4(a0, inv); scale4(a1, inv);
    if (last) {
        float4* o4 = (float4*)(out + (size_t)warp * 512 + DIM);
        o4[lane] = a0; o4[lane + 32] = a1;
    }
    float4 r0, r1;
    r0.x = tf32r(a0.x); r0.y = tf32r(a0.y); r0.z = tf32r(a0.z); r0.w = tf32r(a0.w);
    r1.x = tf32r(a1.x); r1.y = tf32r(a1.y); r1.z = tf32r(a1.z); r1.w = tf32r(a1.w);
    float4* ro = (float4*)(buf + (size_t)warp * KCAT);
    ro[lane] = r0; ro[lane + 32] = r1;
}

// ------------------- mma.sync tf32 GEMM + fused LSTM -----------------------
// CTA tile 128x128, 8 warps (warp 32x64), BK=32, 3-stage pipeline.
// Smem: XOR-swizzled 128B rows, 32KB/stage -> 96KB total -> 2 CTAs/SM.
#define NSTAGE 3
#define TILE_BYTES 16384               // 128 rows x 128B
#define STAGE_BYTES (2 * TILE_BYTES)   // 32768
#define GEMM_SMEM (NSTAGE * STAGE_BYTES)

__global__ void __launch_bounds__(256, 2)
gemm_lstm_kernel(const float* __restrict__ A, float* __restrict__ Anext,
                 float* __restrict__ out, int M, int last) {
    extern __shared__ __align__(128) char smem[];
    uint32_t sbase = smem_u32(smem);
    const int tid = threadIdx.x;
    const int wid = tid >> 5, lane = tid & 31;
    const int wm = wid & 3, wn = wid >> 2;      // 4x2 warp grid
    const int bn = blockIdx.x, bm = blockIdx.y;
    const uint32_t sw = lane >> 2;              // swizzle xor for fragment loads

    auto load_chunk = [&](int c, int s) {
#pragma unroll
        for (int i = 0; i < 8; ++i) {
            int q = i * 256 + tid;
            int tile = q >> 10;
            int idx = q & 1023;
            int row = idx >> 3, c4 = idx & 7;
            uint32_t dst = sbase + s * STAGE_BYTES + tile * TILE_BYTES
                         + (uint32_t)row * 128 + (uint32_t)((c4 ^ (row & 7)) << 4);
            const float* src;
            if (tile == 0) {
                int rA = bm * 128 + row; if (rA >= M) rA = M - 1;
                src = A + (size_t)rA * KCAT + c * 32 + c4 * 4;
            } else {
                src = g_Wcat + (size_t)(bn * 128 + row) * KCAT + c * 32 + c4 * 4;
            }
            CP_ASYNC16(dst, src);
        }
        CP_COMMIT();
    };

#pragma unroll
    for (int s = 0; s < NSTAGE; ++s) load_chunk(s, s);

    float acc[2][8][4];
#pragma unroll
    for (int mt = 0; mt < 2; ++mt)
#pragma unroll
        for (int nt = 0; nt < 8; ++nt)
#pragma unroll
            for (int r = 0; r < 4; ++r) acc[mt][nt][r] = 0.f;

    // stage-relative fragment bases (row*128 + (lane&3)*4)
    const uint32_t a_rel = (uint32_t)(wm * 32 + (lane >> 2)) * 128 + (lane & 3) * 4;
    const uint32_t b_rel = (uint32_t)(wn * 64 + (lane >> 2)) * 128 + (lane & 3) * 4;

    for (int c = 0; c < 16; ++c) {
        const int s = c % NSTAGE;
        asm volatile("cp.async.wait_group %0;" :: "n"(NSTAGE - 1) : "memory");
        __syncthreads();
        uint32_t aS = sbase + s * STAGE_BYTES + a_rel;
        uint32_t bS = sbase + s * STAGE_BYTES + TILE_BYTES + b_rel;
#pragma unroll
        for (int kk = 0; kk < 4; ++kk) {
            uint32_t c0 = ((uint32_t)(kk * 2) ^ sw) << 4;
            uint32_t c1 = ((uint32_t)(kk * 2 + 1) ^ sw) << 4;
            uint32_t af[2][4], bf[8][2];
#pragma unroll
            for (int mt = 0; mt < 2; ++mt) {
                uint32_t base = aS + mt * 2048;
                LDS32(af[mt][0], base + c0);
                LDS32(af[mt][1], base + 1024 + c0);
                LDS32(af[mt][2], base + c1);
                LDS32(af[mt][3], base + 1024 + c1);
            }
#pragma unroll
            for (int nt = 0; nt < 8; ++nt) {
                uint32_t base = bS + nt * 1024;
                LDS32(bf[nt][0], base + c0);
                LDS32(bf[nt][1], base + c1);
            }
#pragma unroll
            for (int mt = 0; mt < 2; ++mt)
#pragma unroll
                for (int nt = 0; nt < 8; ++nt)
                    mma_tf32(acc[mt][nt], af[mt], bf[nt]);
        }
        __syncthreads();
        if (c + NSTAGE < 16) load_chunk(c + NSTAGE, s);
        else                 CP_COMMIT();   // empty group keeps wait_group aligned
    }

    // ---- epilogue: bias + LSTM; gate-interleaved cols (col = 4*d + q) ----
    const int sub = lane & 3;
    const bool odd = sub & 1;
    const int dhalf = sub >> 1;
#pragma unroll
    for (int mt = 0; mt < 2; ++mt) {
        int g = bm * 128 + wm * 32 + mt * 16 + (lane >> 2) + (odd ? 8 : 0);
#pragma unroll
        for (int nt = 0; nt < 8; ++nt) {
            float c0 = acc[mt][nt][0], c1 = acc[mt][nt][1];
            float c2 = acc[mt][nt][2], c3 = acc[mt][nt][3];
            int colb = bn * 128 + wn * 64 + nt * 8 + sub * 2;
            float bi0 = __ldg(g_bsum + colb), bi1 = __ldg(g_bsum + colb + 1);
            c0 += bi0; c1 += bi1; c2 += bi0; c3 += bi1;
            float t0 = __shfl_xor_sync(0xffffffffu, c0, 1);
            float t1 = __shfl_xor_sync(0xffffffffu, c1, 1);
            float t2 = __shfl_xor_sync(0xffffffffu, c2, 1);
            float t3 = __shfl_xor_sync(0xffffffffu, c3, 1);
            float gi = odd ? t2 : c0;
            float gf = odd ? t3 : c1;
            float gg = odd ? c2 : t0;
            float go = odd ? c3 : t1;
            int d = ((bn * 128 + wn * 64 + nt * 8) >> 2) + dhalf;
            if (g < M) {
                float cold = g_c[g * DIM + d];
                float cn = sigm(gf) * cold + sigm(gi) * ftanh(gg);
                float h = sigm(go) * ftanh(cn);
                g_c[g * DIM + d] = cn;
                Anext[(size_t)g * KCAT + DIM + d] = tf32r(h);
                if (last) out[(size_t)g * 512 + d] = h;
            }
        }
    }
}

// ------------------------------ launch -------------------------------------
extern "C" void kernel_launch(void* const* d_in, const int* in_sizes, int n_in,
                              void* d_out, int out_size) {
    const float* x     = (const float*)d_in[0];
    const int*   batch = (const int*)d_in[1];
    const float* W_ih  = (const float*)d_in[3];
    const float* W_hh  = (const float*)d_in[4];
    const float* b_ih  = (const float*)d_in[5];
    const float* b_hh  = (const float*)d_in[6];
    float* out = (float*)d_out;

    int N = in_sizes[1];
    int G = out_size / (2 * DIM);

    float *A0, *A1;
    cudaGetSymbolAddress((void**)&A0, g_A0);
    cudaGetSymbolAddress((void**)&A1, g_A1);

    cudaFuncSetAttribute(gemm_lstm_kernel,
                         cudaFuncAttributeMaxDynamicSharedMemorySize, GEMM_SMEM);

    prep_w_kernel<<<(GDIM4 * KCAT + 255) / 256, 256>>>(W_ih, W_hh, b_ih, b_hh);
    offsets_kernel<<<(N + 255) / 256, 256>>>(batch, N, G);
    zero_state_kernel<<<(G * DIM + 255) / 256, 256>>>(G);

    dim3 gemm_grid(GDIM4 / 128, (G + 127) / 128);
    for (int it = 0; it < 6; ++it) {
        float* cur = (it & 1) ? A1 : A0;
        float* nxt = (it & 1) ? A0 : A1;
        int last = (it == 5) ? 1 : 0;
        attn_kernel<<<(G * 32 + 127) / 128, 128>>>(x, cur, out, G, last);
        gemm_lstm_kernel<<<gemm_grid, 256, GEMM_SMEM>>>(cur, nxt, out, G, last);
    }
}

// round 5
// speedup vs baseline: 2.8385x; 1.0516x over previous
#include <cuda_runtime.h>
#include <cuda_bf16.h>
#include <math.h>
#include <cstdint>

// ---------------------------------------------------------------------------
// Set2Set readout, 6 iterations of {attention readout, LSTM}.
// attn: block-per-graph, 4 warps + online-softmax merge.
// GEMM: mma.sync tf32, single-sync multistage pipeline, LSTM fused epilogue.
// ---------------------------------------------------------------------------

#define DIM 256
#define GDIM4 1024
#define KCAT 512
#define MAXG 8192

__device__ int   g_offs[MAXG + 1];
__device__ float g_A0[MAXG * KCAT];     // [readout(256) | h(256)], tf32-rounded
__device__ float g_A1[MAXG * KCAT];
__device__ float g_Wcat[GDIM4 * KCAT];  // gate-interleaved rows: r = 4*d + q
__device__ float g_bsum[GDIM4];
__device__ float g_c[MAXG * DIM];

// ----------------------------- helpers ------------------------------------
__device__ __forceinline__ uint32_t smem_u32(const void* p) {
    uint32_t a;
    asm("{ .reg .u64 t; cvta.to.shared.u64 t, %1; cvt.u32.u64 %0, t; }"
        : "=r"(a) : "l"(p));
    return a;
}
__device__ __forceinline__ float tf32r(float x) {
    uint32_t u;
    asm("cvt.rna.tf32.f32 %0, %1;" : "=r"(u) : "f"(x));
    return __uint_as_float(u);
}
__device__ __forceinline__ float sigm(float v) { return 1.f / (1.f + __expf(-v)); }
__device__ __forceinline__ float ftanh(float v) {
    float e = __expf(2.f * v);
    return 1.f - 2.f / (e + 1.f);
}

#define LDS32(r, a) asm volatile("ld.shared.b32 %0, [%1];" : "=r"(r) : "r"(a))
#define CP_ASYNC16(dst, src) \
    asm volatile("cp.async.cg.shared.global [%0], [%1], 16;" :: "r"(dst), "l"(src) : "memory")
#define CP_COMMIT() asm volatile("cp.async.commit_group;" ::: "memory")

__device__ __forceinline__ void mma_tf32(float* c, const uint32_t* a, const uint32_t* b) {
    asm volatile(
        "mma.sync.aligned.m16n8k8.row.col.f32.tf32.tf32.f32 "
        "{%0,%1,%2,%3}, {%4,%5,%6,%7}, {%8,%9}, {%0,%1,%2,%3};"
        : "+f"(c[0]), "+f"(c[1]), "+f"(c[2]), "+f"(c[3])
        : "r"(a[0]), "r"(a[1]), "r"(a[2]), "r"(a[3]), "r"(b[0]), "r"(b[1]));
}

// --------------------------- prep kernels ---------------------------------
__global__ void prep_w_kernel(const float* __restrict__ W_ih,
                              const float* __restrict__ W_hh,
                              const float* __restrict__ b_ih,
                              const float* __restrict__ b_hh) {
    int idx = blockIdx.x * blockDim.x + threadIdx.x;
    if (idx < GDIM4 * KCAT) {
        int r = idx / KCAT, k = idx % KCAT;
        int d = r >> 2, q = r & 3;
        int n = q * DIM + d;
        float w = (k < DIM) ? W_ih[n * DIM + k] : W_hh[n * DIM + (k - DIM)];
        g_Wcat[idx] = tf32r(w);
        if (k == 0) g_bsum[r] = b_ih[n] + b_hh[n];
    }
}

__global__ void offsets_kernel(const int* __restrict__ batch, int N, int G) {
    int i = blockIdx.x * blockDim.x + threadIdx.x;
    if (i >= N) return;
    int cur = batch[i];
    if (i == 0) { for (int g = 0; g <= cur; ++g) g_offs[g] = 0; }
    else { int prev = batch[i - 1]; for (int g = prev + 1; g <= cur; ++g) g_offs[g] = i; }
    if (i == N - 1) { for (int g = cur + 1; g <= G; ++g) g_offs[g] = N; }
}

__global__ void zero_state_kernel(int G) {
    int idx = blockIdx.x * blockDim.x + threadIdx.x;
    if (idx >= G * DIM) return;
    int g = idx >> 8, d = idx & 255;
    g_c[idx] = 0.f;
    g_A0[g * KCAT + DIM + d] = 0.f;
}

// --------------------- fused attention + readout --------------------------
__device__ __forceinline__ float dot8(float4 a0, float4 a1, float4 h0, float4 h1) {
    float p = a0.x * h0.x;
    p = fmaf(a0.y, h0.y, p); p = fmaf(a0.z, h0.z, p); p = fmaf(a0.w, h0.w, p);
    p = fmaf(a1.x, h1.x, p); p = fmaf(a1.y, h1.y, p);
    p = fmaf(a1.z, h1.z, p); p = fmaf(a1.w, h1.w, p);
    return p;
}
__device__ __forceinline__ void scale4(float4& a, float s) {
    a.x *= s; a.y *= s; a.z *= s; a.w *= s;
}
__device__ __forceinline__ void fma4(float4& a, float4 x, float e) {
    a.x = fmaf(x.x, e, a.x); a.y = fmaf(x.y, e, a.y);
    a.z = fmaf(x.z, e, a.z); a.w = fmaf(x.w, e, a.w);
}

// One block (128 thr, 4 warps) per graph; warps split nodes stride-4;
// online softmax per warp (m0 = 0), merged in smem.
__global__ void __launch_bounds__(128)
attn_kernel(const float* __restrict__ x, float* __restrict__ buf,
            float* __restrict__ out, int G, int last) {
    int g = blockIdx.x;
    int lane = threadIdx.x & 31, wid = threadIdx.x >> 5;
    int vs = g_offs[g], ve = g_offs[g + 1];

    __shared__ float sm[4], sd[4];
    __shared__ float4 sacc[4][64];     // [warp][dim/4]

    const float4* hb = (const float4*)(buf + (size_t)g * KCAT + DIM);
    float4 h0 = hb[lane], h1 = hb[lane + 32];
    float4 a0 = {0.f, 0.f, 0.f, 0.f}, a1 = {0.f, 0.f, 0.f, 0.f};
    float m = 0.f, dd = 0.f;

    int v = vs + wid;
    for (; v + 4 < ve; v += 8) {       // nodes v and v+4 (stride-4 interleave)
        const float4* xA = (const float4*)(x + (size_t)v * DIM);
        const float4* xB = (const float4*)(x + (size_t)(v + 4) * DIM);
        float4 A0 = __ldcs(xA + lane), A1 = __ldcs(xA + lane + 32);
        float4 B0 = __ldcs(xB + lane), B1 = __ldcs(xB + lane + 32);
        float pA = dot8(A0, A1, h0, h1);
        float pB = dot8(B0, B1, h0, h1);
#pragma unroll
        for (int o = 16; o; o >>= 1) {
            pA += __shfl_xor_sync(0xffffffffu, pA, o);
            pB += __shfl_xor_sync(0xffffffffu, pB, o);
        }
        float mn = fmaxf(m, fmaxf(pA, pB));
        float sc = __expf(m - mn), eA = __expf(pA - mn), eB = __expf(pB - mn);
        dd = dd * sc + eA + eB;
        scale4(a0, sc); scale4(a1, sc);
        fma4(a0, A0, eA); fma4(a1, A1, eA);
        fma4(a0, B0, eB); fma4(a1, B1, eB);
        m = mn;
    }
    if (v < ve) {
        const float4* xA = (const float4*)(x + (size_t)v * DIM);
        float4 A0 = __ldcs(xA + lane), A1 = __ldcs(xA + lane + 32);
        float p = dot8(A0, A1, h0, h1);
#pragma unroll
        for (int o = 16; o; o >>= 1) p += __shfl_xor_sync(0xffffffffu, p, o);
        float mn = fmaxf(m, p);
        float sc = __expf(m - mn), e = __expf(p - mn);
        dd = dd * sc + e;
        scale4(a0, sc); scale4(a1, sc);
        fma4(a0, A0, e); fma4(a1, A1, e);
        m = mn;
    }

    if (lane == 0) { sm[wid] = m; sd[wid] = dd; }
    sacc[wid][lane] = a0;
    sacc[wid][lane + 32] = a1;
    __syncthreads();

    float M = fmaxf(fmaxf(sm[0], sm[1]), fmaxf(sm[2], sm[3]));
    float e0 = __expf(sm[0] - M), e1 = __expf(sm[1] - M);
    float e2 = __expf(sm[2] - M), e3 = __expf(sm[3] - M);
    float D = sd[0] * e0 + sd[1] * e1 + sd[2] * e2 + sd[3] * e3;
    float inv = 1.f / (D + 1e-8f);

    // 128 threads x 2 float4 slots = 256 dims
    int t = threadIdx.x;
#pragma unroll
    for (int half = 0; half < 2; ++half) {
        int slot = t & 63;                 // float4 index 0..63
        int w4 = (t >> 6) + half * 2;      // unused; keep simple below
        (void)w4;
        int idx = half * 64 + slot;        // 0..127? need 64 slots total
        // simpler: thread t handles slot t%64 when t<64*? -- handle below
        if (half == 0 && t < 64) idx = t; else if (half == 1 && t >= 64) idx = t - 64 + 0;
        // fallthrough handled by explicit code below
        break;
    }
    // Each of the 128 threads merges one float4 slot twice is wrong; do: 64 slots,
    // threads 0..63 handle slot t, threads 64..127 idle for merge width 64? No:
    // 64 float4 slots = 256 dims; split: thread t (0..127) handles slot t/2 halves.
    // Simplest correct: threads 0..63 do all 64 slots.
    if (t < 64) {
        float4 r;
        float4 p0 = sacc[0][t], p1 = sacc[1][t], p2 = sacc[2][t], p3 = sacc[3][t];
        r.x = (p0.x * e0 + p1.x * e1 + p2.x * e2 + p3.x * e3) * inv;
        r.y = (p0.y * e0 + p1.y * e1 + p2.y * e2 + p3.y * e3) * inv;
        r.z = (p0.z * e0 + p1.z * e1 + p2.z * e2 + p3.z * e3) * inv;
        r.w = (p0.w * e0 + p1.w * e1 + p2.w * e2 + p3.w * e3) * inv;
        if (last) {
            float4* o4 = (float4*)(out + (size_t)g * 512 + DIM);
            o4[t] = r;
        }
        float4 rr;
        rr.x = tf32r(r.x); rr.y = tf32r(r.y); rr.z = tf32r(r.z); rr.w = tf32r(r.w);
        float4* ro = (float4*)(buf + (size_t)g * KCAT);
        ro[t] = rr;
    }
}

// ------------------- mma.sync tf32 GEMM + fused LSTM -----------------------
// CTA tile 128x128, 8 warps (warp 32x64), BK=32, 3-stage single-sync pipeline.
#define NSTAGE 3
#define TILE_BYTES 16384               // 128 rows x 128B
#define STAGE_BYTES (2 * TILE_BYTES)   // 32768
#define GEMM_SMEM (NSTAGE * STAGE_BYTES)

__global__ void __launch_bounds__(256, 2)
gemm_lstm_kernel(const float* __restrict__ A, float* __restrict__ Anext,
                 float* __restrict__ out, int M, int last) {
    extern __shared__ __align__(128) char smem[];
    uint32_t sbase = smem_u32(smem);
    const int tid = threadIdx.x;
    const int wid = tid >> 5, lane = tid & 31;
    const int wm = wid & 3, wn = wid >> 2;
    const int bn = blockIdx.x, bm = blockIdx.y;
    const uint32_t sw = lane >> 2;

    auto load_chunk = [&](int c, int s) {
#pragma unroll
        for (int i = 0; i < 8; ++i) {
            int q = i * 256 + tid;
            int tile = q >> 10;
            int idx = q & 1023;
            int row = idx >> 3, c4 = idx & 7;
            uint32_t dst = sbase + s * STAGE_BYTES + tile * TILE_BYTES
                         + (uint32_t)row * 128 + (uint32_t)((c4 ^ (row & 7)) << 4);
            const float* src;
            if (tile == 0) {
                int rA = bm * 128 + row; if (rA >= M) rA = M - 1;
                src = A + (size_t)rA * KCAT + c * 32 + c4 * 4;
            } else {
                src = g_Wcat + (size_t)(bn * 128 + row) * KCAT + c * 32 + c4 * 4;
            }
            CP_ASYNC16(dst, src);
        }
        CP_COMMIT();
    };

    // prefetch NSTAGE-1 chunks
    load_chunk(0, 0);
    load_chunk(1, 1);

    float acc[2][8][4];
#pragma unroll
    for (int mt = 0; mt < 2; ++mt)
#pragma unroll
        for (int nt = 0; nt < 8; ++nt)
#pragma unroll
            for (int r = 0; r < 4; ++r) acc[mt][nt][r] = 0.f;

    const uint32_t a_rel = (uint32_t)(wm * 32 + (lane >> 2)) * 128 + (lane & 3) * 4;
    const uint32_t b_rel = (uint32_t)(wn * 64 + (lane >> 2)) * 128 + (lane & 3) * 4;

    for (int c = 0; c < 16; ++c) {
        const int s = c % NSTAGE;
        asm volatile("cp.async.wait_group 1;" ::: "memory");
        __syncthreads();
        // load chunk c+2 into stage (c+2)%3 (consumed at iter c-1; safe after sync)
        if (c + 2 < 16) load_chunk(c + 2, (c + 2) % NSTAGE);
        else            CP_COMMIT();    // keep group count aligned for wait_group
        uint32_t aS = sbase + s * STAGE_BYTES + a_rel;
        uint32_t bS = sbase + s * STAGE_BYTES + TILE_BYTES + b_rel;
#pragma unroll
        for (int kk = 0; kk < 4; ++kk) {
            uint32_t c0 = ((uint32_t)(kk * 2) ^ sw) << 4;
            uint32_t c1 = ((uint32_t)(kk * 2 + 1) ^ sw) << 4;
            uint32_t af[2][4], bf[8][2];
#pragma unroll
            for (int mt = 0; mt < 2; ++mt) {
                uint32_t base = aS + mt * 2048;
                LDS32(af[mt][0], base + c0);
                LDS32(af[mt][1], base + 1024 + c0);
                LDS32(af[mt][2], base + c1);
                LDS32(af[mt][3], base + 1024 + c1);
            }
#pragma unroll
            for (int nt = 0; nt < 8; ++nt) {
                uint32_t base = bS + nt * 1024;
                LDS32(bf[nt][0], base + c0);
                LDS32(bf[nt][1], base + c1);
            }
#pragma unroll
            for (int mt = 0; mt < 2; ++mt)
#pragma unroll
                for (int nt = 0; nt < 8; ++nt)
                    mma_tf32(acc[mt][nt], af[mt], bf[nt]);
        }
    }

    // ---- epilogue: bias + LSTM; gate-interleaved cols (col = 4*d + q) ----
    const int sub = lane & 3;
    const bool odd = sub & 1;
    const int dhalf = sub >> 1;
#pragma unroll
    for (int mt = 0; mt < 2; ++mt) {
        int g = bm * 128 + wm * 32 + mt * 16 + (lane >> 2) + (odd ? 8 : 0);
#pragma unroll
        for (int nt = 0; nt < 8; ++nt) {
            float c0 = acc[mt][nt][0], c1 = acc[mt][nt][1];
            float c2 = acc[mt][nt][2], c3 = acc[mt][nt][3];
            int colb = bn * 128 + wn * 64 + nt * 8 + sub * 2;
            float bi0 = __ldg(g_bsum + colb), bi1 = __ldg(g_bsum + colb + 1);
            c0 += bi0; c1 += bi1; c2 += bi0; c3 += bi1;
            float t0 = __shfl_xor_sync(0xffffffffu, c0, 1);
            float t1 = __shfl_xor_sync(0xffffffffu, c1, 1);
            float t2 = __shfl_xor_sync(0xffffffffu, c2, 1);
            float t3 = __shfl_xor_sync(0xffffffffu, c3, 1);
            float gi = odd ? t2 : c0;
            float gf = odd ? t3 : c1;
            float gg = odd ? c2 : t0;
            float go = odd ? c3 : t1;
            int d = ((bn * 128 + wn * 64 + nt * 8) >> 2) + dhalf;
            if (g < M) {
                float cold = g_c[g * DIM + d];
                float cn = sigm(gf) * cold + sigm(gi) * ftanh(gg);
                float h = sigm(go) * ftanh(cn);
                g_c[g * DIM + d] = cn;
                Anext[(size_t)g * KCAT + DIM + d] = tf32r(h);
                if (last) out[(size_t)g * 512 + d] = h;
            }
        }
    }
}

// ------------------------------ launch -------------------------------------
extern "C" void kernel_launch(void* const* d_in, const int* in_sizes, int n_in,
                              void* d_out, int out_size) {
    const float* x     = (const float*)d_in[0];
    const int*   batch = (const int*)d_in[1];
    const float* W_ih  = (const float*)d_in[3];
    const float* W_hh  = (const float*)d_in[4];
    const float* b_ih  = (const float*)d_in[5];
    const float* b_hh  = (const float*)d_in[6];
    float* out = (float*)d_out;

    int N = in_sizes[1];
    int G = out_size / (2 * DIM);

    float *A0, *A1;
    cudaGetSymbolAddress((void**)&A0, g_A0);
    cudaGetSymbolAddress((void**)&A1, g_A1);

    cudaFuncSetAttribute(gemm_lstm_kernel,
                         cudaFuncAttributeMaxDynamicSharedMemorySize, GEMM_SMEM);

    prep_w_kernel<<<(GDIM4 * KCAT + 255) / 256, 256>>>(W_ih, W_hh, b_ih, b_hh);
    offsets_kernel<<<(N + 255) / 256, 256>>>(batch, N, G);
    zero_state_kernel<<<(G * DIM + 255) / 256, 256>>>(G);

    dim3 gemm_grid(GDIM4 / 128, (G + 127) / 128);
    for (int it = 0; it < 6; ++it) {
        float* cur = (it & 1) ? A1 : A0;
        float* nxt = (it & 1) ? A0 : A1;
        int last = (it == 5) ? 1 : 0;
        attn_kernel<<<G, 128>>>(x, cur, out, G, last);
        gemm_lstm_kernel<<<gemm_grid, 256, GEMM_SMEM>>>(cur, nxt, out, G, last);
    }
}